// round 2
// baseline (speedup 1.0000x reference)
#include <cuda_runtime.h>

#define NEMB 512

__device__ float g_sorted_val[NEMB];
__device__ int   g_sorted_idx[NEMB];
__device__ float g_loss_accum;

// ---------------------------------------------------------------------------
// Kernel A: bitonic-sort the 512-entry scalar codebook (value + original
// index payload) into g_sorted_*, and zero the loss accumulator.
// One block, 512 threads.
// ---------------------------------------------------------------------------
__global__ void sort_codebook_kernel(const float* __restrict__ emb) {
    __shared__ float sv[NEMB];
    __shared__ int   si[NEMB];
    const int tid = threadIdx.x;
    sv[tid] = emb[tid];
    si[tid] = tid;
    __syncthreads();

    for (int k = 2; k <= NEMB; k <<= 1) {
        for (int j = k >> 1; j > 0; j >>= 1) {
            const int ixj = tid ^ j;
            if (ixj > tid) {
                const float a = sv[tid];
                const float b = sv[ixj];
                const bool ascending = ((tid & k) == 0);
                if ((a > b) == ascending) {
                    sv[tid] = b; sv[ixj] = a;
                    const int ti = si[tid];
                    si[tid] = si[ixj]; si[ixj] = ti;
                }
            }
            __syncthreads();
        }
    }

    g_sorted_val[tid] = sv[tid];
    g_sorted_idx[tid] = si[tid];
    if (tid == 0) g_loss_accum = 0.0f;
}

// ---------------------------------------------------------------------------
// Nearest-codeword pick with reference-exact semantics:
// compare fp32-rounded squared distances; on equality pick smaller original
// index (jnp.argmin first-min).
// ---------------------------------------------------------------------------
__device__ __forceinline__ float nearest(const float* __restrict__ sval,
                                         const int* __restrict__ sidx,
                                         float xv, float* __restrict__ sqerr) {
    // lower_bound: smallest lo with sval[lo] >= xv. Range 512 -> 10 halvings.
    int lo = 0, hi = NEMB;
    #pragma unroll
    for (int it = 0; it < 10; it++) {
        const int mid = (lo + hi) >> 1;
        if (hi > lo) {
            if (sval[mid] < xv) lo = mid + 1; else hi = mid;
        }
    }

    float q, d2;
    if (lo == 0) {
        q = sval[0];
        const float d = __fadd_rn(xv, -q);
        d2 = __fmul_rn(d, d);
    } else if (lo == NEMB) {
        q = sval[NEMB - 1];
        const float d = __fadd_rn(xv, -q);
        d2 = __fmul_rn(d, d);
    } else {
        const float a = sval[lo - 1];
        const float b = sval[lo];
        const float da = __fadd_rn(xv, -a);
        const float db = __fadd_rn(xv, -b);
        const float da2 = __fmul_rn(da, da);
        const float db2 = __fmul_rn(db, db);
        bool pick_a;
        if (da2 < db2)       pick_a = true;
        else if (db2 < da2)  pick_a = false;
        else                 pick_a = (sidx[lo - 1] < sidx[lo]);
        q  = pick_a ? a   : b;
        d2 = pick_a ? da2 : db2;
    }
    *sqerr = d2;
    return q;
}

// ---------------------------------------------------------------------------
// Kernel B: per-element nearest-codebook lookup, float4-vectorized.
// Accumulates sum of squared quantization error via warp reduce + one
// atomicAdd per warp.
// ---------------------------------------------------------------------------
__global__ void quantize_kernel(const float* __restrict__ x,
                                float* __restrict__ out,
                                int n) {
    __shared__ float sval[NEMB];
    __shared__ int   sidx[NEMB];
    for (int i = threadIdx.x; i < NEMB; i += blockDim.x) {
        sval[i] = g_sorted_val[i];
        sidx[i] = g_sorted_idx[i];
    }
    __syncthreads();

    const int tid4 = blockIdx.x * blockDim.x + threadIdx.x;
    const int base = tid4 * 4;

    float local = 0.0f;

    if (base + 3 < n) {
        const float4 v = *reinterpret_cast<const float4*>(x + base);
        float vv[4] = {v.x, v.y, v.z, v.w};
        float qq[4];

        #pragma unroll
        for (int e = 0; e < 4; e++) {
            float d2;
            qq[e] = nearest(sval, sidx, vv[e], &d2);
            local += d2;
        }

        float4 o;
        o.x = qq[0]; o.y = qq[1]; o.z = qq[2]; o.w = qq[3];
        *reinterpret_cast<float4*>(out + base) = o;
    } else {
        for (int i = base; i < n && i < base + 4; i++) {
            float d2;
            const float q = nearest(sval, sidx, x[i], &d2);
            out[i] = q;
            local += d2;
        }
    }

    // warp reduce
    #pragma unroll
    for (int off = 16; off > 0; off >>= 1)
        local += __shfl_xor_sync(0xFFFFFFFFu, local, off);

    if ((threadIdx.x & 31) == 0)
        atomicAdd(&g_loss_accum, local);
}

// ---------------------------------------------------------------------------
// Kernel C: finalize loss = (1 + 0.25) * mean(sq err)
// ---------------------------------------------------------------------------
__global__ void finalize_kernel(float* __restrict__ out, int n, int write_loss) {
    if (write_loss)
        out[n] = 1.25f * g_loss_accum / (float)n;
}

extern "C" void kernel_launch(void* const* d_in, const int* in_sizes, int n_in,
                              void* d_out, int out_size) {
    const float* x   = (const float*)d_in[0];   // pre_quantized, 16*1*128*128
    const float* emb = (const float*)d_in[1];   // emb_weight, 512*1
    float* out = (float*)d_out;

    const int n = in_sizes[0];                  // 262144

    sort_codebook_kernel<<<1, NEMB>>>(emb);

    const int threads = 256;
    const int blocks = (n / 4 + threads - 1) / threads;
    quantize_kernel<<<blocks, threads>>>(x, out, n);

    finalize_kernel<<<1, 1>>>(out, n, out_size > n ? 1 : 0);
}